// round 11
// baseline (speedup 1.0000x reference)
#include <cuda_runtime.h>
#include <cstdint>

// SpikeFP32ScaleBy2K — rows of 32 {0,1} floats = big-endian FP32 bit pattern.
// out = x with exponent += K (mod 256), K = 8-bit two's-complement
// (0x80|m_k[0..6]) >> (7 - ((e_k-127)&7)), negated if s_k; passthrough when
// k's exp+mantissa bits are all zero. Only elements 1..8 change.
//
// R11 = persistent grid-stride version of the R9 core. Evidence: kernel is
// pinned at ~85-86% of HBM spec regardless of MLP (4/6/8) and ALU level
// (44-66%); the remaining 4-6us is the wall-vs-ncu gap = multi-wave CTA
// scheduling (≈28 waves at grid=32768). Launch ONE wave (148 SMs × 8 CTAs,
// regs≈29 @ 256thr → 8 CTAs/SM resident) and loop: zero wave transitions,
// prologue + per-lane constants amortized over ~28 iterations.
//   - GROUPS=2: 4 front-batched LDG.128/thread per iteration
//   - no shared memory, no __syncthreads; default-cached loads and stores
//   - element-order combined word, ONE 3-step shfl_xor OR-butterfly/group
//   - 32-bit indexing
//
// Combined word C (element-order, bit = element value):
//   [0:12)   x elements 0..11   (lanes c=0..2; only bits 1..8 consumed)
//   [12:28)  k elements 0..15   (lanes c=0..3)
//   [28]     OR of k elements 16..31 (lanes c=4..7)

static constexpr int GROUPS = 2;                 // 4 rows/group, 8 rows/iter
static constexpr unsigned ONEF = 0x3F800000u;
static constexpr int PERSIST_BLOCKS = 148 * 8;   // one full wave at occ 8
static constexpr int THREADS = 256;

__device__ __forceinline__ unsigned pack_nib(uint4 u) {
    // components are exactly 0x00000000 or 0x3F800000
    unsigned a = min(u.x, 1u), b = min(u.y, 1u);
    unsigned c = min(u.z, 1u), d = min(u.w, 1u);
    return a | (b << 1) | (c << 2) | (d << 3);
}

__global__ void __launch_bounds__(THREADS, 8)
spike_scale_kernel(const uint4* __restrict__ x4,
                   const uint4* __restrict__ k4,
                   uint4* __restrict__ out4,
                   unsigned nrows) {
    const unsigned lane = threadIdx.x & 31u;
    const unsigned c    = lane & 7u;             // float4 chunk within row
    const unsigned sub  = lane >> 3;             // row within 4-row group
    const unsigned s4   = c * 4u;                // first element idx of chunk

    // per-lane constants (computed once, reused across all iterations)
    const unsigned Ax   = (c <= 2u) ? (0xFu << s4) : 0u;        // x field
    const unsigned Ak   = (c <= 3u) ? (0xFu << (s4 + 12u)) : 0u;// k field
    const unsigned s4k  = (s4 + 12u) & 31u;
    const unsigned m0   = (c >= 4u) ? ~0u : 0u;  // k hi-half OR contributor
    const unsigned remm = (c == 0u) ? 0xEu : (c == 1u) ? 0xFu
                        : (c == 2u) ? 0x1u : 0u; // exponent components
    const unsigned sh_e = (23u + s4) & 31u;      // enew-bit slice position

    const unsigned warp_id =
        blockIdx.x * (THREADS >> 5) + (threadIdx.x >> 5);
    const unsigned n_warps = gridDim.x * (THREADS >> 5);
    const unsigned rows_per_iter = 4u * GROUPS;          // 8
    const unsigned stride_rows = n_warps * rows_per_iter;

    // Grid-stride over 8-row tiles. nrows is a multiple of 8 in practice so
    // interior tiles are always full; keep a cheap per-group guard anyway.
    for (unsigned row0 = warp_id * rows_per_iter; row0 < nrows;
         row0 += stride_rows) {
        uint4 xv[GROUPS], kv[GROUPS];
        unsigned idx[GROUPS], safem[GROUPS];
        const bool full = (row0 + rows_per_iter) <= nrows;

        #pragma unroll
        for (int g = 0; g < GROUPS; g++) {
            unsigned row = row0 + 4u * g + sub;
            unsigned ok  = full | (row < nrows);
            safem[g] = 0u - (unsigned)ok;
            unsigned r = ok ? row : (nrows - 1u);  // clamp keeps loads legal
            idx[g] = r * 8u + c;                   // fits 32-bit
            xv[g] = x4[idx[g]];
            kv[g] = k4[idx[g]];
        }

        #pragma unroll
        for (int g = 0; g < GROUPS; g++) {
            unsigned nibX = pack_nib(xv[g]);
            unsigned nibK = pack_nib(kv[g]);
            unsigned kOr  = (kv[g].x | kv[g].y | kv[g].z | kv[g].w) & m0;

            unsigned C = ((nibX << s4) & Ax)
                       | ((nibK << s4k) & Ak)
                       | (min(kOr, 1u) << 28);

            C |= __shfl_xor_sync(~0u, C, 1);     // OR-butterfly (8-lane grp)
            C |= __shfl_xor_sync(~0u, C, 2);
            C |= __shfl_xor_sync(~0u, C, 4);

            // ── scalar circuit (reversals once, on the broadcast word) ──
            unsigned B    = __brev(C);
            unsigned ex   = (B >> 23) & 0xFFu;   // x elems 1..8, LSB=elem8
            unsigned ek   = (B >> 11) & 0xFFu;   // k elems 1..8
            unsigned val  = 0x80u | ((B >> 4) & 0x7Fu);  // 1.m_k[0..6]
            unsigned rs   = (6u - ek) & 7u;      // = 7 - ((ek-127)&7)
            unsigned kabs = val >> rs;
            unsigned neg  = 0u - ((C >> 12) & 1u);       // s_k
            unsigned kf   = (kabs ^ neg) - neg;
            unsigned enew = ex + kf;             // low 8 bits valid
            unsigned knz4 = (C & 0x1FFFE000u) ? 0xFu : 0u; // k exp|mant != 0

            // output nibble: enew bits for exponent comps, else own nibX
            unsigned sel    = remm & knz4;
            unsigned en_nib = __brev(enew) >> sh_e;
            unsigned no     = (en_nib & sel) | (nibX & ~sel);

            uint4 o;
            o.x = (0u - (no        & 1u)) & ONEF;
            o.y = (0u - ((no >> 1) & 1u)) & ONEF;
            o.z = (0u - ((no >> 2) & 1u)) & ONEF;
            o.w = (0u - ((no >> 3) & 1u)) & ONEF;
            if (safem[g]) out4[idx[g]] = o;      // default-cached store
        }
    }
}

extern "C" void kernel_launch(void* const* d_in, const int* in_sizes, int n_in,
                              void* d_out, int out_size) {
    const uint4* x4 = (const uint4*)d_in[0];
    const uint4* k4 = (const uint4*)d_in[1];
    uint4* out4 = (uint4*)d_out;

    unsigned nrows = (unsigned)(in_sizes[0] / 32);

    // One persistent wave; cap grid for tiny inputs.
    unsigned tiles = (nrows + 8u * GROUPS - 1u) / (8u * GROUPS) * 8u;
    unsigned warps_needed = (nrows + 4u * GROUPS - 1u) / (4u * GROUPS);
    unsigned blocks_needed = (warps_needed + (THREADS / 32) - 1u) / (THREADS / 32);
    (void)tiles;
    unsigned blocks = PERSIST_BLOCKS < blocks_needed ? PERSIST_BLOCKS
                                                     : blocks_needed;
    if (blocks == 0) blocks = 1;

    spike_scale_kernel<<<blocks, THREADS>>>(x4, k4, out4, nrows);
}

// round 12
// speedup vs baseline: 1.1360x; 1.1360x over previous
#include <cuda_runtime.h>
#include <cstdint>

// SpikeFP32ScaleBy2K — rows of 32 {0,1} floats = big-endian FP32 bit pattern.
// out = x with exponent += K (mod 256), K = 8-bit two's-complement
// (0x80|m_k[0..6]) >> (7 - ((e_k-127)&7)), negated if s_k; passthrough when
// k's exp+mantissa bits are all zero. Only elements 1..8 change.
//
// R12 = R9 compute core + R5 caching policy (the session's two best
// measurements, combined):
//   - __ldcs loads AND __stcs stores: all three streams are touch-once;
//     evict-first was the policy of the best-measured round (R5, 115.8us)
//   - GROUPS=2: 4 front-batched LDG.128/thread (best MLP point; 6 and 8
//     both measured worse)
//   - classic grid (one CTA per 64 rows) — persistent loop measured -14%
//   - no shared memory, no __syncthreads, 32-bit indexing
//   - element-order combined word, ONE 3-step shfl_xor OR-butterfly/group,
//     single __brev on the broadcast word, per-lane nibble output select
//
// Combined word C (element-order, bit = element value):
//   [0:12)   x elements 0..11   (lanes c=0..2; only bits 1..8 consumed)
//   [12:28)  k elements 0..15   (lanes c=0..3)
//   [28]     OR of k elements 16..31 (lanes c=4..7)

static constexpr int GROUPS = 2;                 // 4 rows/group, 8 rows/warp
static constexpr unsigned ONEF = 0x3F800000u;

__device__ __forceinline__ unsigned pack_nib(uint4 u) {
    // components are exactly 0x00000000 or 0x3F800000
    unsigned a = min(u.x, 1u), b = min(u.y, 1u);
    unsigned c = min(u.z, 1u), d = min(u.w, 1u);
    return a | (b << 1) | (c << 2) | (d << 3);
}

__global__ void __launch_bounds__(256)
spike_scale_kernel(const uint4* __restrict__ x4,
                   const uint4* __restrict__ k4,
                   uint4* __restrict__ out4,
                   unsigned nrows) {
    const unsigned lane = threadIdx.x & 31u;
    const unsigned c    = lane & 7u;             // float4 chunk within row
    const unsigned sub  = lane >> 3;             // row within 4-row group
    const unsigned s4   = c * 4u;                // first element idx of chunk

    // per-lane constants
    const unsigned Ax   = (c <= 2u) ? (0xFu << s4) : 0u;        // x field
    const unsigned Ak   = (c <= 3u) ? (0xFu << (s4 + 12u)) : 0u;// k field
    const unsigned s4k  = (s4 + 12u) & 31u;
    const unsigned m0   = (c >= 4u) ? ~0u : 0u;  // k hi-half OR contributor
    const unsigned remm = (c == 0u) ? 0xEu : (c == 1u) ? 0xFu
                        : (c == 2u) ? 0x1u : 0u; // exponent components
    const unsigned sh_e = (23u + s4) & 31u;      // enew-bit slice position

    const unsigned warp_id = blockIdx.x * (blockDim.x >> 5) + (threadIdx.x >> 5);
    const unsigned row0 = warp_id * (4u * GROUPS);
    if (row0 >= nrows) return;                   // warp-uniform

    uint4 xv[GROUPS], kv[GROUPS];
    unsigned idx[GROUPS], safem[GROUPS];
    const bool full = (row0 + 4u * GROUPS) <= nrows;

    #pragma unroll
    for (int g = 0; g < GROUPS; g++) {
        unsigned row = row0 + 4u * g + sub;
        unsigned ok  = full | (row < nrows);
        safem[g] = 0u - (unsigned)ok;
        unsigned r = ok ? row : (nrows - 1u);    // clamp keeps loads in-bounds
        idx[g] = r * 8u + c;                     // fits 32-bit
        xv[g] = __ldcs(&x4[idx[g]]);             // streaming (touch-once)
        kv[g] = __ldcs(&k4[idx[g]]);
    }

    #pragma unroll
    for (int g = 0; g < GROUPS; g++) {
        unsigned nibX = pack_nib(xv[g]);
        unsigned nibK = pack_nib(kv[g]);
        unsigned kOr  = (kv[g].x | kv[g].y | kv[g].z | kv[g].w) & m0;

        unsigned C = ((nibX << s4) & Ax)
                   | ((nibK << s4k) & Ak)
                   | (min(kOr, 1u) << 28);

        C |= __shfl_xor_sync(~0u, C, 1);         // OR-butterfly (8-lane group)
        C |= __shfl_xor_sync(~0u, C, 2);
        C |= __shfl_xor_sync(~0u, C, 4);

        // ── scalar circuit (reversals once, on the broadcast word) ──
        unsigned B    = __brev(C);
        unsigned ex   = (B >> 23) & 0xFFu;       // x elements 1..8, LSB=elem8
        unsigned ek   = (B >> 11) & 0xFFu;       // k elements 1..8
        unsigned val  = 0x80u | ((B >> 4) & 0x7Fu);   // 1.m_k[0..6]
        unsigned rs   = (6u - ek) & 7u;          // = 7 - ((ek-127)&7)
        unsigned kabs = val >> rs;
        unsigned neg  = 0u - ((C >> 12) & 1u);   // s_k
        unsigned kf   = (kabs ^ neg) - neg;
        unsigned enew = ex + kf;                 // low 8 bits valid
        unsigned knz4 = (C & 0x1FFFE000u) ? 0xFu : 0u;  // k exp|mant nonzero

        // per-lane output nibble: enew bits for exponent comps, else own nibX
        unsigned sel    = remm & knz4;
        unsigned en_nib = __brev(enew) >> sh_e;  // bit t = enew bit (8-s4-t)
        unsigned no     = (en_nib & sel) | (nibX & ~sel);

        uint4 o;
        o.x = (0u - (no        & 1u)) & ONEF;    // raw 1.0f / 0.0f patterns
        o.y = (0u - ((no >> 1) & 1u)) & ONEF;
        o.z = (0u - ((no >> 2) & 1u)) & ONEF;
        o.w = (0u - ((no >> 3) & 1u)) & ONEF;
        if (safem[g]) __stcs(&out4[idx[g]], o);  // streaming store
    }
}

extern "C" void kernel_launch(void* const* d_in, const int* in_sizes, int n_in,
                              void* d_out, int out_size) {
    const uint4* x4 = (const uint4*)d_in[0];
    const uint4* k4 = (const uint4*)d_in[1];
    uint4* out4 = (uint4*)d_out;

    unsigned nrows = (unsigned)(in_sizes[0] / 32);

    const int threads = 256;                     // 8 warps
    const int rows_per_block = 8 * 4 * GROUPS;   // 64
    int blocks = (int)((nrows + rows_per_block - 1) / rows_per_block);

    spike_scale_kernel<<<blocks, threads>>>(x4, k4, out4, nrows);
}

// round 13
// speedup vs baseline: 1.1558x; 1.0175x over previous
#include <cuda_runtime.h>
#include <cstdint>

// SpikeFP32ScaleBy2K — rows of 32 {0,1} floats = big-endian FP32 bit pattern.
// out = x with exponent += K (mod 256) where K = 8-bit two's-complement
// trunc-ish(|k|) = (0x80|m_k[0..6]) >> (7 - ((e_k-127)&7)), negated if s_k;
// passthrough when k's exp+mantissa bits are all zero.
// Only elements 1..8 (exponent) ever change; sign+mantissa pass through.
//
// R13 = exact resubmission of the session-best R5 configuration (115.8us).
// Rationale: the kernel is at the LTS (L2) throughput ceiling — ~6300 B/cyc
// full-chip ≈ 6.9 TB/s, path-independent — with an irreducible 768 MiB of
// 2R+1W traffic => wall floor ≈ 116.7us. Every lever tested (MLP 4/6/8,
// store/load caching policy, SMEM LUT, persistent grid, ALU 44-66%) left
// the wall inside [115.8, 118.7]us. The highest-EV submission is the exact
// source that produced the observed minimum.

static constexpr int GROUPS = 2;                  // 4 rows/group, 8 rows/warp
static constexpr unsigned ONEF = 0x3F800000u;

__device__ __forceinline__ unsigned pack_nib(uint4 u) {
    // components are exactly 0x00000000 or 0x3F800000
    unsigned a = min(u.x, 1u), b = min(u.y, 1u);
    unsigned c = min(u.z, 1u), d = min(u.w, 1u);
    return a | (b << 1) | (c << 2) | (d << 3);
}

__global__ void __launch_bounds__(256)
spike_scale_kernel(const uint4* __restrict__ x4,
                   const uint4* __restrict__ k4,
                   uint4* __restrict__ out4,
                   unsigned nrows) {
    const unsigned lane = threadIdx.x & 31u;
    const unsigned c    = lane & 7u;          // float4 chunk within row
    const unsigned sub  = lane >> 3;          // row within 4-row group
    const unsigned eb   = c * 4u;             // first element index of chunk

    // ── per-lane constants (hoisted out of the group loop) ──
    // exponent-field placement: rev4(nib) bit j (element eb+3-j) -> bit (5-eb)+j
    const unsigned shl = (c <= 1u) ? (5u - eb) : 0u;
    const unsigned shr = (c >= 2u) ? (eb - 5u) : 0u;
    const unsigned Mx  = (c == 0u) ? 0xE0u : (c == 1u) ? 0x1Eu
                       : (c == 2u) ? 0x01u : 0u;
    const unsigned shm = 28u - eb;            // mantissa-field placement
    const unsigned Mkm = (c == 2u) ? 0x700000u : (c == 3u) ? 0xF0000u : 0u;
    const unsigned Msk = (c == 0u) ? 1u : 0u; // sign bit source (element 0)
    const unsigned m0  = (c == 0u) ? 0u : ~0u;// exclude k element0 from knz
    unsigned rmm[4], sho[4];                  // output replace mask + bit pos
    #pragma unroll
    for (int t = 0; t < 4; t++) {
        unsigned e = eb + (unsigned)t;
        bool rep = (e >= 1u && e <= 8u);      // exponent elements only
        rmm[t] = rep ? ~0u : 0u;
        sho[t] = rep ? (8u - e) : 0u;
    }

    const unsigned warp_id = blockIdx.x * (blockDim.x >> 5) + (threadIdx.x >> 5);
    const unsigned row0 = warp_id * (4u * GROUPS);
    if (row0 >= nrows) return;                // warp-uniform

    uint4 xv[GROUPS], kv[GROUPS];
    unsigned idx[GROUPS];
    unsigned safem[GROUPS];                   // ~0 if row valid

    const bool full = (row0 + 4u * GROUPS) <= nrows;

    #pragma unroll
    for (int g = 0; g < GROUPS; g++) {
        unsigned row = row0 + 4u * g + sub;
        unsigned ok  = full | (row < nrows);
        safem[g] = 0u - (unsigned)ok;
        unsigned r = ok ? row : (nrows - 1u); // clamp: keep loads in-bounds
        idx[g] = r * 8u + c;                  // fits 32-bit (max 2^24)
        xv[g] = __ldcs(&x4[idx[g]]);
        kv[g] = __ldcs(&k4[idx[g]]);
    }

    #pragma unroll
    for (int g = 0; g < GROUPS; g++) {
        unsigned nibX = pack_nib(xv[g]);
        unsigned nibK = pack_nib(kv[g]);
        unsigned rX = __brev(nibX) >> 28;     // 4-bit reverse
        unsigned rK = __brev(nibK) >> 28;

        unsigned kOr = (kv[g].x & m0) | kv[g].y | kv[g].z | kv[g].w;
        unsigned C = (((rX << shl) >> shr) & Mx)
                   | ((((rK << shl) >> shr) & Mx) << 8)
                   | ((rK << shm) & Mkm)
                   | ((nibK & Msk) << 23)
                   | (min(kOr, 1u) << 24);

        C |= __shfl_xor_sync(~0u, C, 1);      // OR-butterfly within 8 lanes
        C |= __shfl_xor_sync(~0u, C, 2);
        C |= __shfl_xor_sync(~0u, C, 4);

        // ── the circuit, in integers ──
        unsigned ex   = C & 0xFFu;
        unsigned ek   = (C >> 8) & 0xFFu;
        unsigned val  = 0x80u | ((C >> 16) & 0x7Fu);   // 1.mmmmmmm
        unsigned rs   = (6u - ek) & 7u;                // 7 - ((ek-127)&7)
        unsigned kabs = val >> rs;
        unsigned neg  = 0u - ((C >> 23) & 1u);         // ~0 if s_k
        unsigned kf   = (kabs ^ neg) - neg;            // conditional negate
        unsigned enew = ex + kf;                       // low 8 bits valid
        unsigned knzm = 0u - ((C >> 24) & 1u);         // ~0 if k != 0

        uint4 o;
        {
            unsigned m, b;
            m = rmm[0] & knzm; b = 0u - ((enew >> sho[0]) & 1u);
            o.x = (ONEF & b & m) | (xv[g].x & ~m);
            m = rmm[1] & knzm; b = 0u - ((enew >> sho[1]) & 1u);
            o.y = (ONEF & b & m) | (xv[g].y & ~m);
            m = rmm[2] & knzm; b = 0u - ((enew >> sho[2]) & 1u);
            o.z = (ONEF & b & m) | (xv[g].z & ~m);
            m = rmm[3] & knzm; b = 0u - ((enew >> sho[3]) & 1u);
            o.w = (ONEF & b & m) | (xv[g].w & ~m);
        }
        if (safem[g]) __stcs(&out4[idx[g]], o);
    }
}

extern "C" void kernel_launch(void* const* d_in, const int* in_sizes, int n_in,
                              void* d_out, int out_size) {
    const uint4* x4 = (const uint4*)d_in[0];
    const uint4* k4 = (const uint4*)d_in[1];
    uint4* out4 = (uint4*)d_out;

    unsigned nrows = (unsigned)(in_sizes[0] / 32);

    const int threads = 256;                            // 8 warps
    const int rows_per_block = 8 * 4 * GROUPS;          // 64
    int blocks = (int)((nrows + rows_per_block - 1) / rows_per_block);

    spike_scale_kernel<<<blocks, threads>>>(x4, k4, out4, nrows);
}